// round 9
// baseline (speedup 1.0000x reference)
#include <cuda_runtime.h>
#include <cuda_bf16.h>
#include <stdint.h>
#include <math.h>

#define CBN 6
#define CSZ 1024
#define TPB 256
#define RPC 128          // rows per CTA (16 per warp)
#define EPS 0.5f         // proven rescue window (R7/R8: rel_err 0.0)

// per-lane-region b-frag layout: region idx (0..31) stride 130 uint2 (=1040B),
// element nt (0..127) at +nt. 16B pad per region kills LDS.128 bank conflicts.
__device__ __align__(16) uint2 g_bfrag[CBN * 32 * 130];
__device__ float  g_c2[CBN * CSZ];
__device__ float  g_L[CBN * CSZ];
__device__ float  g_p2[CBN * CSZ];
__device__ int    g_lc[CBN];
__device__ double g_part[CBN * 256];
__device__ unsigned int g_ctr = 0;

struct __align__(16) Smem {
    uint4  bfrag[32 * 65];       // 33280B (32 regions x 65 uint4)
    unsigned short xaf[RPC * 8]; //  2048B bf16(-2x) a-frags
    float  x2sh[RPC];            //   512B
    float  bitsv[RPC];           //   512B
    double dscr[RPC];            //  1024B
    int    flag;
};

__device__ __forceinline__ float sqrt_approx(float v) {
    float r; asm("sqrt.approx.f32 %0, %1;" : "=f"(r) : "f"(v)); return r;
}

__device__ __forceinline__ void hmma16816(float& d0, float& d1, float& d2, float& d3,
                                          uint32_t a0, uint32_t a1, uint32_t a2, uint32_t a3,
                                          uint32_t b0, uint32_t b1) {
    asm volatile(
        "mma.sync.aligned.m16n8k16.row.col.f32.bf16.bf16.f32 "
        "{%0,%1,%2,%3}, {%4,%5,%6,%7}, {%8,%9}, {%10,%11,%12,%13};"
        : "=f"(d0), "=f"(d1), "=f"(d2), "=f"(d3)
        : "r"(a0), "r"(a1), "r"(a2), "r"(a3), "r"(b0), "r"(b1),
          "f"(0.0f), "f"(0.0f), "f"(0.0f), "f"(0.0f));
}

// ---------------- prep: per-cb tables (proven numerics chain) ----------------
__global__ void __launch_bounds__(TPB) prep_kernel(
    const float* __restrict__ codebook,
    const float* __restrict__ logits)
{
    __shared__ float scr[TPB];
    const int tid = threadIdx.x;
    const int cb  = blockIdx.x;

    float4 lv = *reinterpret_cast<const float4*>(logits + (size_t)cb * CSZ + tid * 4);
    float lm = fmaxf(fmaxf(lv.x, lv.y), fmaxf(lv.z, lv.w));
    scr[tid] = lm; __syncthreads();
    #pragma unroll
    for (int off = 128; off > 0; off >>= 1) {
        if (tid < off) scr[tid] = fmaxf(scr[tid], scr[tid + off]);
        __syncthreads();
    }
    const float mx = scr[0]; __syncthreads();
    float lmn = fminf(fminf(lv.x, lv.y), fminf(lv.z, lv.w));
    scr[tid] = lmn; __syncthreads();
    #pragma unroll
    for (int off = 128; off > 0; off >>= 1) {
        if (tid < off) scr[tid] = fminf(scr[tid], scr[tid + off]);
        __syncthreads();
    }
    const bool lc = (scr[0] == mx);
    __syncthreads();
    float es = expf(lv.x - mx) + expf(lv.y - mx) + expf(lv.z - mx) + expf(lv.w - mx);
    scr[tid] = es; __syncthreads();
    #pragma unroll
    for (int off = 128; off > 0; off >>= 1) {
        if (tid < off) scr[tid] += scr[tid + off];
        __syncthreads();
    }
    const float lnS = logf(scr[0]);

    const float INV_LOG2 = 1.4426950408889634f;
    #pragma unroll
    for (int j = 0; j < 4; j++) {
        int s = tid * 4 + j;
        const float4* cp = reinterpret_cast<const float4*>(codebook + ((size_t)cb * CSZ + s) * 8);
        float4 c0 = cp[0], c1 = cp[1];
        float q0=c0.x*c0.x,q1=c0.y*c0.y,q2=c0.z*c0.z,q3=c0.w*c0.w;
        float q4=c1.x*c1.x,q5=c1.y*c1.y,q6=c1.z*c1.z,q7=c1.w*c1.w;
        float c2 = ((((((q0+q1)+q2)+q3)+q4)+q5)+q6)+q7;
        float v  = (j==0)?lv.x:(j==1)?lv.y:(j==2)?lv.z:lv.w;
        float p2 = ((v - mx) - lnS) * (-INV_LOG2);
        size_t gi = (size_t)cb * CSZ + s;
        g_c2[gi] = c2;
        g_L[gi]  = p2 / 0.005f;
        g_p2[gi] = p2;
        unsigned short e[8];
        e[0]=__bfloat16_as_ushort(__float2bfloat16_rn(c0.x));
        e[1]=__bfloat16_as_ushort(__float2bfloat16_rn(c0.y));
        e[2]=__bfloat16_as_ushort(__float2bfloat16_rn(c0.z));
        e[3]=__bfloat16_as_ushort(__float2bfloat16_rn(c0.w));
        e[4]=__bfloat16_as_ushort(__float2bfloat16_rn(c1.x));
        e[5]=__bfloat16_as_ushort(__float2bfloat16_rn(c1.y));
        e[6]=__bfloat16_as_ushort(__float2bfloat16_rn(c1.z));
        e[7]=__bfloat16_as_ushort(__float2bfloat16_rn(c1.w));
        unsigned short c2b = __bfloat16_as_ushort(__float2bfloat16_rn(c2));
        int nt = s >> 3, g = s & 7;
        uint2* base = &g_bfrag[(size_t)cb * 4160];
        #pragma unroll
        for (int t = 0; t < 4; t++) {
            uint32_t lo = (uint32_t)e[2*t] | ((uint32_t)e[2*t+1] << 16);
            uint32_t hi = (t == 0) ? (uint32_t)c2b : 0u;   // k8 = c2 (pairs a-frag 1.0)
            base[(g * 4 + t) * 130 + nt] = make_uint2(lo, hi);
        }
    }
    if (tid == 0) g_lc[cb] = lc ? 1 : 0;
}

// ---------------- main ----------------
__global__ void __launch_bounds__(TPB, 6)
ecvq_kernel(const float* __restrict__ x,
            const float* __restrict__ codebook,
            float* __restrict__ out, int B)
{
    extern __shared__ unsigned char smem_raw[];
    Smem* sm = reinterpret_cast<Smem*>(smem_raw);

    const int tid = threadIdx.x;
    const int cb  = blockIdx.x;
    const int rowBase = blockIdx.y * RPC;
    const float FINF = __int_as_float(0x7f800000);
    const size_t gb = (size_t)cb * CSZ;

    // ---- copy b-frag tables from gmem (2080 uint4) ----
    {
        const uint4* src = reinterpret_cast<const uint4*>(&g_bfrag[(size_t)cb * 4160]);
        uint4* dst = sm->bfrag;
        #pragma unroll
        for (int i = 0; i < 8; i++) dst[tid + i * TPB] = src[tid + i * TPB];
        if (tid < 2080 - 8 * TPB) dst[tid + 8 * TPB] = src[tid + 8 * TPB];
    }
    const bool lc = (g_lc[cb] != 0);

    // ---- stage x: a-frags bf16(-2x) + exact x2 ----
    if (tid < RPC) {
        int grow = rowBase + tid;
        const float4* xpp = reinterpret_cast<const float4*>(x + (size_t)grow * (CBN * 8) + cb * 8);
        float4 p0 = xpp[0], p1 = xpp[1];
        float q0=p0.x*p0.x,q1=p0.y*p0.y,q2=p0.z*p0.z,q3=p0.w*p0.w;
        float q4=p1.x*p1.x,q5=p1.y*p1.y,q6=p1.z*p1.z,q7=p1.w*p1.w;
        sm->x2sh[tid] = ((((((q0+q1)+q2)+q3)+q4)+q5)+q6)+q7;
        unsigned short* xa = &sm->xaf[tid * 8];
        xa[0]=__bfloat16_as_ushort(__float2bfloat16_rn(-2.0f*p0.x));
        xa[1]=__bfloat16_as_ushort(__float2bfloat16_rn(-2.0f*p0.y));
        xa[2]=__bfloat16_as_ushort(__float2bfloat16_rn(-2.0f*p0.z));
        xa[3]=__bfloat16_as_ushort(__float2bfloat16_rn(-2.0f*p0.w));
        xa[4]=__bfloat16_as_ushort(__float2bfloat16_rn(-2.0f*p1.x));
        xa[5]=__bfloat16_as_ushort(__float2bfloat16_rn(-2.0f*p1.y));
        xa[6]=__bfloat16_as_ushort(__float2bfloat16_rn(-2.0f*p1.z));
        xa[7]=__bfloat16_as_ushort(__float2bfloat16_rn(-2.0f*p1.w));
    }
    __syncthreads();

    // ---- warp tiling: each warp owns 16 rows ----
    const int warp = tid >> 5, lane = tid & 31;
    const int g = lane >> 2, t = lane & 3;
    const int r0 = warp * 16 + g, r1 = r0 + 8;

    const uint32_t a0 = *reinterpret_cast<const uint32_t*>(&sm->xaf[r0 * 8 + t * 2]);
    const uint32_t a1 = *reinterpret_cast<const uint32_t*>(&sm->xaf[r1 * 8 + t * 2]);
    const uint32_t ac = (t == 0) ? 0x00003F80u : 0u;   // bf16(1.0) at k8

    // lane-private contiguous stream: region idx == lane, stride 1040B
    const char* bp = reinterpret_cast<const char*>(sm->bfrag) + lane * 1040;

    // ============ PASS 1: branchless min of score = c2 - 2xc ============
    float m0 = FINF, m1 = FINF;
    #pragma unroll 4
    for (int it = 0; it < 64; it++) {
        uint4 q = *reinterpret_cast<const uint4*>(bp + it * 16);
        float d0, d1, d2, d3, e0, e1, e2, e3;
        hmma16816(d0, d1, d2, d3, a0, a1, ac, ac, q.x, q.y);
        hmma16816(e0, e1, e2, e3, a0, a1, ac, ac, q.z, q.w);
        m0 = fminf(m0, fminf(fminf(d0, d1), fminf(e0, e1)));
        m1 = fminf(m1, fminf(fminf(d2, d3), fminf(e2, e3)));
    }
    m0 = fminf(m0, __shfl_xor_sync(0xffffffffu, m0, 1));
    m0 = fminf(m0, __shfl_xor_sync(0xffffffffu, m0, 2));
    m1 = fminf(m1, __shfl_xor_sync(0xffffffffu, m1, 1));
    m1 = fminf(m1, __shfl_xor_sync(0xffffffffu, m1, 2));

    const float thr0 = lc ? m0 + EPS : FINF;
    const float thr1 = lc ? m1 + EPS : FINF;

    // exact rescore (bit-exact proven chain; rare -> gmem reads OK)
    auto rescue = [&](int s, int r, float& bv, int& bi) {
        const float4* cp = reinterpret_cast<const float4*>(codebook + (gb + s) * 8);
        float4 ca = __ldg(cp), cv = __ldg(cp + 1);
        int grow = rowBase + r;
        const float4* xpp = reinterpret_cast<const float4*>(x + (size_t)grow * (CBN * 8) + cb * 8);
        float4 pa = __ldg(xpp), pb = __ldg(xpp + 1);
        float xc = pa.x * ca.x;
        xc = fmaf(pa.y, ca.y, xc); xc = fmaf(pa.z, ca.z, xc); xc = fmaf(pa.w, ca.w, xc);
        xc = fmaf(pb.x, cv.x, xc); xc = fmaf(pb.y, cv.y, xc);
        xc = fmaf(pb.z, cv.z, xc); xc = fmaf(pb.w, cv.w, xc);
        float d2 = fmaf(-2.0f, xc, sm->x2sh[r]) + __ldg(&g_c2[gb + s]);
        float val = sqrt_approx(fmaxf(d2, 0.0f)) + __ldg(&g_L[gb + s]);
        if (val < bv) { bv = val; bi = s; }
    };

    // ============ PASS 2: fixed-threshold exact rescue ============
    float bv0 = FINF, bv1 = FINF;
    int   bi0 = 0,    bi1 = 0;
    #pragma unroll 2
    for (int it = 0; it < 64; it++) {
        uint4 q = *reinterpret_cast<const uint4*>(bp + it * 16);
        float d0, d1, d2, d3, e0, e1, e2, e3;
        hmma16816(d0, d1, d2, d3, a0, a1, ac, ac, q.x, q.y);
        hmma16816(e0, e1, e2, e3, a0, a1, ac, ac, q.z, q.w);
        bool anyT = (fminf(fminf(d0, d1), fminf(e0, e1)) < thr0)
                  | (fminf(fminf(d2, d3), fminf(e2, e3)) < thr1);
        if (__ballot_sync(0xffffffffu, anyT)) {
            int sA = (2 * it) * 8 + 2 * t;        // first nt of the pair
            int sB = sA + 8;                       // second nt
            if (d0 < thr0) rescue(sA,     r0, bv0, bi0);
            if (d1 < thr0) rescue(sA + 1, r0, bv0, bi0);
            if (d2 < thr1) rescue(sA,     r1, bv1, bi1);
            if (d3 < thr1) rescue(sA + 1, r1, bv1, bi1);
            if (e0 < thr0) rescue(sB,     r0, bv0, bi0);
            if (e1 < thr0) rescue(sB + 1, r0, bv0, bi0);
            if (e2 < thr1) rescue(sB,     r1, bv1, bi1);
            if (e3 < thr1) rescue(sB + 1, r1, bv1, bi1);
        }
    }

    // ---- cross-lane reduce (lowest-index ties) ----
    #pragma unroll
    for (int mref = 1; mref <= 2; mref <<= 1) {
        float ov; int oi;
        ov = __shfl_xor_sync(0xffffffffu, bv0, mref); oi = __shfl_xor_sync(0xffffffffu, bi0, mref);
        if (ov < bv0 || (ov == bv0 && oi < bi0)) { bv0 = ov; bi0 = oi; }
        ov = __shfl_xor_sync(0xffffffffu, bv1, mref); oi = __shfl_xor_sync(0xffffffffu, bi1, mref);
        if (ov < bv1 || (ov == bv1 && oi < bi1)) { bv1 = ov; bi1 = oi; }
    }

    if (t == 0) {
        const size_t ixBase = (size_t)B * (CBN * 8) + 1;
        int rr[2] = {r0, r1};
        int bb[2] = {bi0, bi1};
        #pragma unroll
        for (int q = 0; q < 2; q++) {
            int r = rr[q], bi = bb[q];
            int grow = rowBase + r;
            const float4* cp = reinterpret_cast<const float4*>(codebook + (gb + bi) * 8);
            float4* op = reinterpret_cast<float4*>(out + (size_t)grow * (CBN * 8) + cb * 8);
            op[0] = __ldg(cp);
            op[1] = __ldg(cp + 1);
            out[ixBase + (size_t)grow * CBN + cb] = (float)bi;
            sm->bitsv[r] = __ldg(&g_p2[gb + bi]);
        }
    }
    __syncthreads();

    // ---- per-CTA deterministic bits partial ----
    double* bd = sm->dscr;
    if (tid < RPC) bd[tid] = (double)sm->bitsv[tid];
    __syncthreads();
    #pragma unroll
    for (int off = 64; off > 0; off >>= 1) {
        if (tid < off) bd[tid] += bd[tid + off];
        __syncthreads();
    }
    const int nCTA = gridDim.x * gridDim.y;
    if (tid == 0) {
        g_part[blockIdx.x * gridDim.y + blockIdx.y] = bd[0];
        __threadfence();
        unsigned int old = atomicAdd(&g_ctr, 1u);
        sm->flag = (old == (unsigned)(nCTA - 1)) ? 1 : 0;
    }
    __syncthreads();

    // ---- last CTA: deterministic final bits sum ----
    if (sm->flag) {
        double acc = 0.0;
        for (int i = tid; i < nCTA; i += TPB)
            acc += ((volatile double*)g_part)[i];
        __syncthreads();
        bd[tid & 127] = 0.0;   // reuse scratch safely
        __syncthreads();
        if (tid < 128) bd[tid] = acc;
        __syncthreads();
        if (tid >= 128) { /* fold upper half */ }
        if (tid < 128) {
            // add upper-half accs via shuffle-free smem: gather from threads 128..255
        }
        // simpler: full 256-wide reduce in two stages using dscr twice
        __syncthreads();
        // stage 1: threads 128..255 add their acc into lower slots
        if (tid >= 128) atomicAdd((double*)&bd[tid - 128], 0.0); // no-op placeholder
        __syncthreads();
        // deterministic: lane-order serial add of the two halves
        if (tid < 128) {
            // bring in acc of tid+128 via shared float? use warp shuffle not possible across warps.
        }
        // Final deterministic tree over 256 values: store accs in a fresh pass
        __syncthreads();
        {
            __shared__ double sfin[TPB];
            sfin[tid] = acc;
            __syncthreads();
            #pragma unroll
            for (int off = 128; off > 0; off >>= 1) {
                if (tid < off) sfin[tid] += sfin[tid + off];
                __syncthreads();
            }
            if (tid == 0) {
                out[(size_t)B * (CBN * 8)] = (float)sfin[0];
                g_ctr = 0;   // reset for next graph replay
            }
        }
    }
}

extern "C" void kernel_launch(void* const* d_in, const int* in_sizes, int n_in,
                              void* d_out, int out_size)
{
    const float* x = nullptr; const float* codebook = nullptr; const float* logits = nullptr;
    int B = 0;
    for (int i = 0; i < n_in; i++) {
        if (in_sizes[i] == CBN * CSZ)          logits   = (const float*)d_in[i];
        else if (in_sizes[i] == CBN * CSZ * 8) codebook = (const float*)d_in[i];
        else { x = (const float*)d_in[i]; B = in_sizes[i] / (CBN * 8); }
    }
    float* out = (float*)d_out;

    size_t smem = sizeof(Smem);
    cudaFuncSetAttribute(ecvq_kernel,
                         cudaFuncAttributeMaxDynamicSharedMemorySize, (int)smem);

    prep_kernel<<<CBN, TPB>>>(codebook, logits);
    dim3 grid(CBN, B / RPC);
    ecvq_kernel<<<grid, TPB, smem>>>(x, codebook, out, B);
}

// round 10
// speedup vs baseline: 1.5093x; 1.5093x over previous
#include <cuda_runtime.h>
#include <cuda_bf16.h>
#include <stdint.h>
#include <math.h>

#define CBN 6
#define CSZ 1024
#define TPB 256
#define RPC 128          // rows per CTA (16 per warp)
#define EPS 0.5f         // proven rescue window (R7/R8: rel_err 0.0)

// per-lane-region b-frag layout: region idx (0..31) = g*4+t, stride 130 uint2
// (=1040B, odd 16B multiple -> conflict-free LDS.128), element nt at +nt.
__device__ __align__(16) uint2 g_bfrag[CBN * 32 * 130];
__device__ float  g_c2[CBN * CSZ];
__device__ float  g_L[CBN * CSZ];
__device__ float  g_p2[CBN * CSZ];
__device__ int    g_lc[CBN];
__device__ double g_part[CBN * 256];
__device__ unsigned int g_ctr = 0;

struct __align__(16) Smem {
    uint4  bfrag[32 * 65];       // 33280B
    float  c2arr[CSZ];           //  4KB  exact c2 (rescue)
    float  Lsh[CSZ];             //  4KB  L (rescue)
    float4 xfp[2 * RPC];         //  4KB  exact fp32 x (rescue)
    unsigned short xaf[RPC * 8]; //  2KB  bf16(-2x) a-frags
    float  x2sh[RPC];            // 512B
    float  bitsv[RPC];           // 512B
    double dscr[TPB];            //  2KB
    int    flag;
};

__device__ __forceinline__ float sqrt_approx(float v) {
    float r; asm("sqrt.approx.f32 %0, %1;" : "=f"(r) : "f"(v)); return r;
}

__device__ __forceinline__ void hmma16816(float& d0, float& d1, float& d2, float& d3,
                                          uint32_t a0, uint32_t a1, uint32_t a2, uint32_t a3,
                                          uint32_t b0, uint32_t b1) {
    asm volatile(
        "mma.sync.aligned.m16n8k16.row.col.f32.bf16.bf16.f32 "
        "{%0,%1,%2,%3}, {%4,%5,%6,%7}, {%8,%9}, {%10,%11,%12,%13};"
        : "=f"(d0), "=f"(d1), "=f"(d2), "=f"(d3)
        : "r"(a0), "r"(a1), "r"(a2), "r"(a3), "r"(b0), "r"(b1),
          "f"(0.0f), "f"(0.0f), "f"(0.0f), "f"(0.0f));
}

// ---------------- prep: per-cb tables (proven numerics chain) ----------------
__global__ void __launch_bounds__(TPB) prep_kernel(
    const float* __restrict__ codebook,
    const float* __restrict__ logits)
{
    __shared__ float scr[TPB];
    const int tid = threadIdx.x;
    const int cb  = blockIdx.x;

    float4 lv = *reinterpret_cast<const float4*>(logits + (size_t)cb * CSZ + tid * 4);
    float lm = fmaxf(fmaxf(lv.x, lv.y), fmaxf(lv.z, lv.w));
    scr[tid] = lm; __syncthreads();
    #pragma unroll
    for (int off = 128; off > 0; off >>= 1) {
        if (tid < off) scr[tid] = fmaxf(scr[tid], scr[tid + off]);
        __syncthreads();
    }
    const float mx = scr[0]; __syncthreads();
    float lmn = fminf(fminf(lv.x, lv.y), fminf(lv.z, lv.w));
    scr[tid] = lmn; __syncthreads();
    #pragma unroll
    for (int off = 128; off > 0; off >>= 1) {
        if (tid < off) scr[tid] = fminf(scr[tid], scr[tid + off]);
        __syncthreads();
    }
    const bool lc = (scr[0] == mx);
    __syncthreads();
    float es = expf(lv.x - mx) + expf(lv.y - mx) + expf(lv.z - mx) + expf(lv.w - mx);
    scr[tid] = es; __syncthreads();
    #pragma unroll
    for (int off = 128; off > 0; off >>= 1) {
        if (tid < off) scr[tid] += scr[tid + off];
        __syncthreads();
    }
    const float lnS = logf(scr[0]);

    const float INV_LOG2 = 1.4426950408889634f;
    #pragma unroll
    for (int j = 0; j < 4; j++) {
        int s = tid * 4 + j;
        const float4* cp = reinterpret_cast<const float4*>(codebook + ((size_t)cb * CSZ + s) * 8);
        float4 c0 = cp[0], c1 = cp[1];
        float q0=c0.x*c0.x,q1=c0.y*c0.y,q2=c0.z*c0.z,q3=c0.w*c0.w;
        float q4=c1.x*c1.x,q5=c1.y*c1.y,q6=c1.z*c1.z,q7=c1.w*c1.w;
        float c2 = ((((((q0+q1)+q2)+q3)+q4)+q5)+q6)+q7;
        float v  = (j==0)?lv.x:(j==1)?lv.y:(j==2)?lv.z:lv.w;
        float p2 = ((v - mx) - lnS) * (-INV_LOG2);
        size_t gi = (size_t)cb * CSZ + s;
        g_c2[gi] = c2;
        g_L[gi]  = p2 / 0.005f;
        g_p2[gi] = p2;
        unsigned short e[8];
        e[0]=__bfloat16_as_ushort(__float2bfloat16_rn(c0.x));
        e[1]=__bfloat16_as_ushort(__float2bfloat16_rn(c0.y));
        e[2]=__bfloat16_as_ushort(__float2bfloat16_rn(c0.z));
        e[3]=__bfloat16_as_ushort(__float2bfloat16_rn(c0.w));
        e[4]=__bfloat16_as_ushort(__float2bfloat16_rn(c1.x));
        e[5]=__bfloat16_as_ushort(__float2bfloat16_rn(c1.y));
        e[6]=__bfloat16_as_ushort(__float2bfloat16_rn(c1.z));
        e[7]=__bfloat16_as_ushort(__float2bfloat16_rn(c1.w));
        unsigned short c2b = __bfloat16_as_ushort(__float2bfloat16_rn(c2));
        int nt = s >> 3, g = s & 7;
        uint2* base = &g_bfrag[(size_t)cb * 4160];
        #pragma unroll
        for (int t = 0; t < 4; t++) {
            uint32_t lo = (uint32_t)e[2*t] | ((uint32_t)e[2*t+1] << 16);
            uint32_t hi = (t == 0) ? (uint32_t)c2b : 0u;   // k8 = c2 (pairs a-frag 1.0)
            base[(g * 4 + t) * 130 + nt] = make_uint2(lo, hi);
        }
    }
    if (tid == 0) g_lc[cb] = lc ? 1 : 0;
}

// ---------------- main ----------------
__global__ void __launch_bounds__(TPB, 4)
ecvq_kernel(const float* __restrict__ x,
            const float* __restrict__ codebook,
            float* __restrict__ out, int B)
{
    extern __shared__ unsigned char smem_raw[];
    Smem* sm = reinterpret_cast<Smem*>(smem_raw);

    const int tid = threadIdx.x;
    const int cb  = blockIdx.x;
    const int rowBase = blockIdx.y * RPC;
    const float FINF = __int_as_float(0x7f800000);
    const size_t gb = (size_t)cb * CSZ;

    // ---- copy per-cb tables from gmem ----
    {
        const uint4* src = reinterpret_cast<const uint4*>(&g_bfrag[(size_t)cb * 4160]);
        uint4* dst = sm->bfrag;
        #pragma unroll
        for (int i = 0; i < 8; i++) dst[tid + i * TPB] = src[tid + i * TPB];
        if (tid < 2080 - 8 * TPB) dst[tid + 8 * TPB] = src[tid + 8 * TPB];
        #pragma unroll
        for (int i = 0; i < 4; i++) {
            int s = tid + i * TPB;
            sm->c2arr[s] = g_c2[gb + s];
            sm->Lsh[s]   = g_L[gb + s];
        }
    }
    const bool lc = (g_lc[cb] != 0);

    // ---- stage x: a-frags bf16(-2x), exact fp32, x2 ----
    if (tid < RPC) {
        int grow = rowBase + tid;
        const float4* xpp = reinterpret_cast<const float4*>(x + (size_t)grow * (CBN * 8) + cb * 8);
        float4 p0 = xpp[0], p1 = xpp[1];
        sm->xfp[2 * tid] = p0; sm->xfp[2 * tid + 1] = p1;
        float q0=p0.x*p0.x,q1=p0.y*p0.y,q2=p0.z*p0.z,q3=p0.w*p0.w;
        float q4=p1.x*p1.x,q5=p1.y*p1.y,q6=p1.z*p1.z,q7=p1.w*p1.w;
        sm->x2sh[tid] = ((((((q0+q1)+q2)+q3)+q4)+q5)+q6)+q7;
        unsigned short* xa = &sm->xaf[tid * 8];
        xa[0]=__bfloat16_as_ushort(__float2bfloat16_rn(-2.0f*p0.x));
        xa[1]=__bfloat16_as_ushort(__float2bfloat16_rn(-2.0f*p0.y));
        xa[2]=__bfloat16_as_ushort(__float2bfloat16_rn(-2.0f*p0.z));
        xa[3]=__bfloat16_as_ushort(__float2bfloat16_rn(-2.0f*p0.w));
        xa[4]=__bfloat16_as_ushort(__float2bfloat16_rn(-2.0f*p1.x));
        xa[5]=__bfloat16_as_ushort(__float2bfloat16_rn(-2.0f*p1.y));
        xa[6]=__bfloat16_as_ushort(__float2bfloat16_rn(-2.0f*p1.z));
        xa[7]=__bfloat16_as_ushort(__float2bfloat16_rn(-2.0f*p1.w));
    }
    __syncthreads();

    // ---- warp tiling: each warp owns 16 rows ----
    const int warp = tid >> 5, lane = tid & 31;
    const int g = lane >> 2, t = lane & 3;
    const int r0 = warp * 16 + g, r1 = r0 + 8;

    const uint32_t a0 = *reinterpret_cast<const uint32_t*>(&sm->xaf[r0 * 8 + t * 2]);
    const uint32_t a1 = *reinterpret_cast<const uint32_t*>(&sm->xaf[r1 * 8 + t * 2]);
    const uint32_t ac = (t == 0) ? 0x00003F80u : 0u;   // bf16(1.0) at k8

    // lane-private contiguous stream: region idx == lane, stride 1040B
    const char* bp = reinterpret_cast<const char*>(sm->bfrag) + lane * 1040;

    // ============ PASS 1: branchless min of score = c2 - 2xc ============
    float m0 = FINF, m1 = FINF;
    #pragma unroll 4
    for (int it = 0; it < 64; it++) {
        uint4 q = *reinterpret_cast<const uint4*>(bp + it * 16);
        float d0, d1, d2, d3, e0, e1, e2, e3;
        hmma16816(d0, d1, d2, d3, a0, a1, ac, ac, q.x, q.y);
        hmma16816(e0, e1, e2, e3, a0, a1, ac, ac, q.z, q.w);
        m0 = fminf(m0, fminf(fminf(d0, d1), fminf(e0, e1)));
        m1 = fminf(m1, fminf(fminf(d2, d3), fminf(e2, e3)));
    }
    m0 = fminf(m0, __shfl_xor_sync(0xffffffffu, m0, 1));
    m0 = fminf(m0, __shfl_xor_sync(0xffffffffu, m0, 2));
    m1 = fminf(m1, __shfl_xor_sync(0xffffffffu, m1, 1));
    m1 = fminf(m1, __shfl_xor_sync(0xffffffffu, m1, 2));

    const float thr0 = lc ? m0 + EPS : FINF;
    const float thr1 = lc ? m1 + EPS : FINF;

    // exact rescore (bit-exact proven chain; rescue tables in smem as in R8)
    auto rescue = [&](int s, int r, float& bv, int& bi) {
        const float4* cp = reinterpret_cast<const float4*>(codebook + (gb + s) * 8);
        float4 ca = __ldg(cp), cv = __ldg(cp + 1);
        float4 pa = sm->xfp[2 * r], pb = sm->xfp[2 * r + 1];
        float xc = pa.x * ca.x;
        xc = fmaf(pa.y, ca.y, xc); xc = fmaf(pa.z, ca.z, xc); xc = fmaf(pa.w, ca.w, xc);
        xc = fmaf(pb.x, cv.x, xc); xc = fmaf(pb.y, cv.y, xc);
        xc = fmaf(pb.z, cv.z, xc); xc = fmaf(pb.w, cv.w, xc);
        float d2 = fmaf(-2.0f, xc, sm->x2sh[r]) + sm->c2arr[s];
        float val = sqrt_approx(fmaxf(d2, 0.0f)) + sm->Lsh[s];
        if (val < bv) { bv = val; bi = s; }
    };

    // ============ PASS 2: fixed-threshold exact rescue ============
    float bv0 = FINF, bv1 = FINF;
    int   bi0 = 0,    bi1 = 0;
    #pragma unroll 2
    for (int it = 0; it < 64; it++) {
        uint4 q = *reinterpret_cast<const uint4*>(bp + it * 16);
        float d0, d1, d2, d3, e0, e1, e2, e3;
        hmma16816(d0, d1, d2, d3, a0, a1, ac, ac, q.x, q.y);
        hmma16816(e0, e1, e2, e3, a0, a1, ac, ac, q.z, q.w);
        bool anyT = (fminf(fminf(d0, d1), fminf(e0, e1)) < thr0)
                  | (fminf(fminf(d2, d3), fminf(e2, e3)) < thr1);
        if (__ballot_sync(0xffffffffu, anyT)) {
            int sA = (2 * it) * 8 + 2 * t;
            int sB = sA + 8;
            if (d0 < thr0) rescue(sA,     r0, bv0, bi0);
            if (d1 < thr0) rescue(sA + 1, r0, bv0, bi0);
            if (d2 < thr1) rescue(sA,     r1, bv1, bi1);
            if (d3 < thr1) rescue(sA + 1, r1, bv1, bi1);
            if (e0 < thr0) rescue(sB,     r0, bv0, bi0);
            if (e1 < thr0) rescue(sB + 1, r0, bv0, bi0);
            if (e2 < thr1) rescue(sB,     r1, bv1, bi1);
            if (e3 < thr1) rescue(sB + 1, r1, bv1, bi1);
        }
    }

    // ---- cross-lane reduce (lowest-index ties) ----
    #pragma unroll
    for (int mref = 1; mref <= 2; mref <<= 1) {
        float ov; int oi;
        ov = __shfl_xor_sync(0xffffffffu, bv0, mref); oi = __shfl_xor_sync(0xffffffffu, bi0, mref);
        if (ov < bv0 || (ov == bv0 && oi < bi0)) { bv0 = ov; bi0 = oi; }
        ov = __shfl_xor_sync(0xffffffffu, bv1, mref); oi = __shfl_xor_sync(0xffffffffu, bi1, mref);
        if (ov < bv1 || (ov == bv1 && oi < bi1)) { bv1 = ov; bi1 = oi; }
    }

    if (t == 0) {
        const size_t ixBase = (size_t)B * (CBN * 8) + 1;
        int rr[2] = {r0, r1};
        int bb[2] = {bi0, bi1};
        #pragma unroll
        for (int q = 0; q < 2; q++) {
            int r = rr[q], bi = bb[q];
            int grow = rowBase + r;
            const float4* cp = reinterpret_cast<const float4*>(codebook + (gb + bi) * 8);
            float4* op = reinterpret_cast<float4*>(out + (size_t)grow * (CBN * 8) + cb * 8);
            op[0] = __ldg(cp);
            op[1] = __ldg(cp + 1);
            out[ixBase + (size_t)grow * CBN + cb] = (float)bi;
            sm->bitsv[r] = __ldg(&g_p2[gb + bi]);
        }
    }
    __syncthreads();

    // ---- per-CTA deterministic bits partial ----
    double* bd = sm->dscr;
    bd[tid] = (tid < RPC) ? (double)sm->bitsv[tid] : 0.0;
    __syncthreads();
    #pragma unroll
    for (int off = 128; off > 0; off >>= 1) {
        if (tid < off) bd[tid] += bd[tid + off];
        __syncthreads();
    }
    const int nCTA = gridDim.x * gridDim.y;
    if (tid == 0) {
        g_part[blockIdx.x * gridDim.y + blockIdx.y] = bd[0];
        __threadfence();
        unsigned int old = atomicAdd(&g_ctr, 1u);
        sm->flag = (old == (unsigned)(nCTA - 1)) ? 1 : 0;
    }
    __syncthreads();

    // ---- last CTA: deterministic final bits sum ----
    if (sm->flag) {
        double acc = 0.0;
        for (int i = tid; i < nCTA; i += TPB)
            acc += ((volatile double*)g_part)[i];
        __syncthreads();
        bd[tid] = acc;
        __syncthreads();
        #pragma unroll
        for (int off = 128; off > 0; off >>= 1) {
            if (tid < off) bd[tid] += bd[tid + off];
            __syncthreads();
        }
        if (tid == 0) {
            out[(size_t)B * (CBN * 8)] = (float)bd[0];
            g_ctr = 0;   // reset for next graph replay
        }
    }
}

extern "C" void kernel_launch(void* const* d_in, const int* in_sizes, int n_in,
                              void* d_out, int out_size)
{
    const float* x = nullptr; const float* codebook = nullptr; const float* logits = nullptr;
    int B = 0;
    for (int i = 0; i < n_in; i++) {
        if (in_sizes[i] == CBN * CSZ)          logits   = (const float*)d_in[i];
        else if (in_sizes[i] == CBN * CSZ * 8) codebook = (const float*)d_in[i];
        else { x = (const float*)d_in[i]; B = in_sizes[i] / (CBN * 8); }
    }
    float* out = (float*)d_out;

    size_t smem = sizeof(Smem);
    cudaFuncSetAttribute(ecvq_kernel,
                         cudaFuncAttributeMaxDynamicSharedMemorySize, (int)smem);

    prep_kernel<<<CBN, TPB>>>(codebook, logits);
    dim3 grid(CBN, B / RPC);
    ecvq_kernel<<<grid, TPB, smem>>>(x, codebook, out, B);
}

// round 11
// speedup vs baseline: 2.1606x; 1.4315x over previous
#include <cuda_runtime.h>
#include <cuda_bf16.h>
#include <stdint.h>
#include <math.h>

#define CBN 6
#define CSZ 1024
#define TPB 256
#define RPC 128          // rows per CTA (16 per warp)
#define EPS 0.5f         // proven rescue window (R7/R8/R10: rel_err 0.0)
#define QMAX 320         // per-warp queue entries; flush when qn >= QMAX-256

// per-lane-region b-frag layout: region (0..31) = g*4+t, stride 130 uint2
// (=1040B, odd 16B multiple -> conflict-free LDS.128), element nt at +nt.
__device__ __align__(16) uint2 g_bfrag[CBN * 32 * 130];
__device__ float  g_c2[CBN * CSZ];
__device__ float  g_L[CBN * CSZ];
__device__ float  g_p2[CBN * CSZ];
__device__ int    g_lc[CBN];
__device__ double g_part[CBN * 256];
__device__ unsigned int g_ctr = 0;

struct __align__(16) Smem {
    uint4  bfrag[32 * 65];            // 33280B
    float4 xfp[2 * RPC];              //  4096B exact fp32 x (rescue)
    unsigned short xaf[RPC * 8];      //  2048B bf16(-2x) a-frags
    float  x2sh[RPC];                 //   512B
    float  bitsv[RPC];                //   512B
    unsigned int qdat[8 * QMAX];      // 10240B per-warp rescue queues
    unsigned long long rbest[RPC];    //  1024B packed (val_bits<<32)|s per row
    double dscr[TPB];                 //  2048B
    int    flag;
};

__device__ __forceinline__ float sqrt_approx(float v) {
    float r; asm("sqrt.approx.f32 %0, %1;" : "=f"(r) : "f"(v)); return r;
}

__device__ __forceinline__ void hmma16816(float& d0, float& d1, float& d2, float& d3,
                                          uint32_t a0, uint32_t a1, uint32_t a2, uint32_t a3,
                                          uint32_t b0, uint32_t b1) {
    asm volatile(
        "mma.sync.aligned.m16n8k16.row.col.f32.bf16.bf16.f32 "
        "{%0,%1,%2,%3}, {%4,%5,%6,%7}, {%8,%9}, {%10,%11,%12,%13};"
        : "=f"(d0), "=f"(d1), "=f"(d2), "=f"(d3)
        : "r"(a0), "r"(a1), "r"(a2), "r"(a3), "r"(b0), "r"(b1),
          "f"(0.0f), "f"(0.0f), "f"(0.0f), "f"(0.0f));
}

// ---------------- prep: per-cb tables (proven numerics chain) ----------------
__global__ void __launch_bounds__(TPB) prep_kernel(
    const float* __restrict__ codebook,
    const float* __restrict__ logits)
{
    __shared__ float scr[TPB];
    const int tid = threadIdx.x;
    const int cb  = blockIdx.x;

    float4 lv = *reinterpret_cast<const float4*>(logits + (size_t)cb * CSZ + tid * 4);
    float lm = fmaxf(fmaxf(lv.x, lv.y), fmaxf(lv.z, lv.w));
    scr[tid] = lm; __syncthreads();
    #pragma unroll
    for (int off = 128; off > 0; off >>= 1) {
        if (tid < off) scr[tid] = fmaxf(scr[tid], scr[tid + off]);
        __syncthreads();
    }
    const float mx = scr[0]; __syncthreads();
    float lmn = fminf(fminf(lv.x, lv.y), fminf(lv.z, lv.w));
    scr[tid] = lmn; __syncthreads();
    #pragma unroll
    for (int off = 128; off > 0; off >>= 1) {
        if (tid < off) scr[tid] = fminf(scr[tid], scr[tid + off]);
        __syncthreads();
    }
    const bool lc = (scr[0] == mx);
    __syncthreads();
    float es = expf(lv.x - mx) + expf(lv.y - mx) + expf(lv.z - mx) + expf(lv.w - mx);
    scr[tid] = es; __syncthreads();
    #pragma unroll
    for (int off = 128; off > 0; off >>= 1) {
        if (tid < off) scr[tid] += scr[tid + off];
        __syncthreads();
    }
    const float lnS = logf(scr[0]);

    const float INV_LOG2 = 1.4426950408889634f;
    #pragma unroll
    for (int j = 0; j < 4; j++) {
        int s = tid * 4 + j;
        const float4* cp = reinterpret_cast<const float4*>(codebook + ((size_t)cb * CSZ + s) * 8);
        float4 c0 = cp[0], c1 = cp[1];
        float q0=c0.x*c0.x,q1=c0.y*c0.y,q2=c0.z*c0.z,q3=c0.w*c0.w;
        float q4=c1.x*c1.x,q5=c1.y*c1.y,q6=c1.z*c1.z,q7=c1.w*c1.w;
        float c2 = ((((((q0+q1)+q2)+q3)+q4)+q5)+q6)+q7;
        float v  = (j==0)?lv.x:(j==1)?lv.y:(j==2)?lv.z:lv.w;
        float p2 = ((v - mx) - lnS) * (-INV_LOG2);
        size_t gi = (size_t)cb * CSZ + s;
        g_c2[gi] = c2;
        g_L[gi]  = p2 / 0.005f;
        g_p2[gi] = p2;
        unsigned short e[8];
        e[0]=__bfloat16_as_ushort(__float2bfloat16_rn(c0.x));
        e[1]=__bfloat16_as_ushort(__float2bfloat16_rn(c0.y));
        e[2]=__bfloat16_as_ushort(__float2bfloat16_rn(c0.z));
        e[3]=__bfloat16_as_ushort(__float2bfloat16_rn(c0.w));
        e[4]=__bfloat16_as_ushort(__float2bfloat16_rn(c1.x));
        e[5]=__bfloat16_as_ushort(__float2bfloat16_rn(c1.y));
        e[6]=__bfloat16_as_ushort(__float2bfloat16_rn(c1.z));
        e[7]=__bfloat16_as_ushort(__float2bfloat16_rn(c1.w));
        unsigned short c2b = __bfloat16_as_ushort(__float2bfloat16_rn(c2));
        int nt = s >> 3, g = s & 7;
        uint2* base = &g_bfrag[(size_t)cb * 4160];
        #pragma unroll
        for (int t = 0; t < 4; t++) {
            uint32_t lo = (uint32_t)e[2*t] | ((uint32_t)e[2*t+1] << 16);
            uint32_t hi = (t == 0) ? (uint32_t)c2b : 0u;   // k8 = c2 (pairs a-frag 1.0)
            base[(g * 4 + t) * 130 + nt] = make_uint2(lo, hi);
        }
    }
    if (tid == 0) g_lc[cb] = lc ? 1 : 0;
}

// ---------------- main ----------------
__global__ void __launch_bounds__(TPB, 4)
ecvq_kernel(const float* __restrict__ x,
            const float* __restrict__ codebook,
            float* __restrict__ out, int B)
{
    extern __shared__ unsigned char smem_raw[];
    Smem* sm = reinterpret_cast<Smem*>(smem_raw);

    const int tid = threadIdx.x;
    const int cb  = blockIdx.x;
    const int rowBase = blockIdx.y * RPC;
    const float FINF = __int_as_float(0x7f800000);
    const size_t gb = (size_t)cb * CSZ;

    // ---- copy b-frag table from gmem (2080 uint4) ----
    {
        const uint4* src = reinterpret_cast<const uint4*>(&g_bfrag[(size_t)cb * 4160]);
        uint4* dst = sm->bfrag;
        #pragma unroll
        for (int i = 0; i < 8; i++) dst[tid + i * TPB] = src[tid + i * TPB];
        if (tid < 2080 - 8 * TPB) dst[tid + 8 * TPB] = src[tid + 8 * TPB];
    }
    const bool lc = (g_lc[cb] != 0);
    const float Lc = __ldg(&g_L[gb]);   // constant L when lc

    // ---- stage x + init rbest ----
    if (tid < RPC) {
        int grow = rowBase + tid;
        const float4* xpp = reinterpret_cast<const float4*>(x + (size_t)grow * (CBN * 8) + cb * 8);
        float4 p0 = xpp[0], p1 = xpp[1];
        sm->xfp[2 * tid] = p0; sm->xfp[2 * tid + 1] = p1;
        float q0=p0.x*p0.x,q1=p0.y*p0.y,q2=p0.z*p0.z,q3=p0.w*p0.w;
        float q4=p1.x*p1.x,q5=p1.y*p1.y,q6=p1.z*p1.z,q7=p1.w*p1.w;
        sm->x2sh[tid] = ((((((q0+q1)+q2)+q3)+q4)+q5)+q6)+q7;
        unsigned short* xa = &sm->xaf[tid * 8];
        xa[0]=__bfloat16_as_ushort(__float2bfloat16_rn(-2.0f*p0.x));
        xa[1]=__bfloat16_as_ushort(__float2bfloat16_rn(-2.0f*p0.y));
        xa[2]=__bfloat16_as_ushort(__float2bfloat16_rn(-2.0f*p0.z));
        xa[3]=__bfloat16_as_ushort(__float2bfloat16_rn(-2.0f*p0.w));
        xa[4]=__bfloat16_as_ushort(__float2bfloat16_rn(-2.0f*p1.x));
        xa[5]=__bfloat16_as_ushort(__float2bfloat16_rn(-2.0f*p1.y));
        xa[6]=__bfloat16_as_ushort(__float2bfloat16_rn(-2.0f*p1.z));
        xa[7]=__bfloat16_as_ushort(__float2bfloat16_rn(-2.0f*p1.w));
        sm->rbest[tid] = ((unsigned long long)0x7f800000u << 32) | 0xFFFFFFFFull;
    }
    __syncthreads();

    // ---- warp tiling: each warp owns 16 rows ----
    const int warp = tid >> 5, lane = tid & 31;
    const int g = lane >> 2, t = lane & 3;
    const int r0 = warp * 16 + g, r1 = r0 + 8;

    const uint32_t a0 = *reinterpret_cast<const uint32_t*>(&sm->xaf[r0 * 8 + t * 2]);
    const uint32_t a1 = *reinterpret_cast<const uint32_t*>(&sm->xaf[r1 * 8 + t * 2]);
    const uint32_t ac = (t == 0) ? 0x00003F80u : 0u;   // bf16(1.0) at k8
    const unsigned lt = (1u << lane) - 1u;

    const char* bp = reinterpret_cast<const char*>(sm->bfrag) + lane * 1040;

    // exact rescore + publish (bit-exact proven chain; batched, warp-cooperative)
    auto flushq = [&](int n) {
        for (int b = 0; b < n; b += 32) {
            int i = b + lane;
            if (i < n) {
                unsigned e = sm->qdat[warp * QMAX + i];
                int s = (int)(e & 1023u), rl = (int)(e >> 10);
                int r = warp * 16 + rl;
                const float4* cp = reinterpret_cast<const float4*>(codebook + (gb + s) * 8);
                float4 ca = __ldg(cp), cv = __ldg(cp + 1);
                float4 pa = sm->xfp[2 * r], pb = sm->xfp[2 * r + 1];
                float xc = pa.x * ca.x;
                xc = fmaf(pa.y, ca.y, xc); xc = fmaf(pa.z, ca.z, xc); xc = fmaf(pa.w, ca.w, xc);
                xc = fmaf(pb.x, cv.x, xc); xc = fmaf(pb.y, cv.y, xc);
                xc = fmaf(pb.z, cv.z, xc); xc = fmaf(pb.w, cv.w, xc);
                float d2 = fmaf(-2.0f, xc, sm->x2sh[r]) + __ldg(&g_c2[gb + s]);
                float L  = lc ? Lc : __ldg(&g_L[gb + s]);
                float val = sqrt_approx(fmaxf(d2, 0.0f)) + L;
                unsigned long long pk =
                    ((unsigned long long)__float_as_uint(val) << 32) | (unsigned long long)(unsigned)s;
                atomicMin(&sm->rbest[r], pk);
            }
        }
    };

    // ============ PASS 1: branchless min of score = c2 - 2xc ============
    float m0 = FINF, m1 = FINF;
    #pragma unroll 4
    for (int it = 0; it < 64; it++) {
        uint4 q = *reinterpret_cast<const uint4*>(bp + it * 16);
        float d0, d1, d2, d3, e0, e1, e2, e3;
        hmma16816(d0, d1, d2, d3, a0, a1, ac, ac, q.x, q.y);
        hmma16816(e0, e1, e2, e3, a0, a1, ac, ac, q.z, q.w);
        m0 = fminf(m0, fminf(fminf(d0, d1), fminf(e0, e1)));
        m1 = fminf(m1, fminf(fminf(d2, d3), fminf(e2, e3)));
    }
    m0 = fminf(m0, __shfl_xor_sync(0xffffffffu, m0, 1));
    m0 = fminf(m0, __shfl_xor_sync(0xffffffffu, m0, 2));
    m1 = fminf(m1, __shfl_xor_sync(0xffffffffu, m1, 1));
    m1 = fminf(m1, __shfl_xor_sync(0xffffffffu, m1, 2));

    const float thr0 = lc ? m0 + EPS : FINF;
    const float thr1 = lc ? m1 + EPS : FINF;

    // ============ PASS 2: push window candidates to queue ============
    int qn = 0;   // warp-uniform queue count (ballot/popc maintained)

    #define PUSHQ(pred, sval, rlocal) do { \
        unsigned mk = __ballot_sync(0xffffffffu, (pred)); \
        if (pred) sm->qdat[warp * QMAX + qn + __popc(mk & lt)] = \
            (unsigned)((sval) | ((rlocal) << 10)); \
        qn += __popc(mk); \
    } while (0)

    #pragma unroll 2
    for (int it = 0; it < 64; it++) {
        uint4 q = *reinterpret_cast<const uint4*>(bp + it * 16);
        float d0, d1, d2, d3, e0, e1, e2, e3;
        hmma16816(d0, d1, d2, d3, a0, a1, ac, ac, q.x, q.y);
        hmma16816(e0, e1, e2, e3, a0, a1, ac, ac, q.z, q.w);
        bool anyT = (fminf(fminf(d0, d1), fminf(e0, e1)) < thr0)
                  | (fminf(fminf(d2, d3), fminf(e2, e3)) < thr1);
        if (__ballot_sync(0xffffffffu, anyT)) {
            if (qn >= QMAX - 256) { flushq(qn); __syncwarp(); qn = 0; }
            int sA = (2 * it) * 8 + 2 * t;
            int sB = sA + 8;
            PUSHQ(d0 < thr0, sA,     g);
            PUSHQ(d1 < thr0, sA + 1, g);
            PUSHQ(d2 < thr1, sA,     g + 8);
            PUSHQ(d3 < thr1, sA + 1, g + 8);
            PUSHQ(e0 < thr0, sB,     g);
            PUSHQ(e1 < thr0, sB + 1, g);
            PUSHQ(e2 < thr1, sB,     g + 8);
            PUSHQ(e3 < thr1, sB + 1, g + 8);
        }
    }
    __syncwarp();
    flushq(qn);
    __syncwarp();

    // ---- epilogue: lanes 0..15 write their row's winner ----
    if (lane < 16) {
        int r = warp * 16 + lane;
        unsigned long long w = sm->rbest[r];
        int bi = (int)(unsigned)(w & 0xFFFFFFFFull);
        int grow = rowBase + r;
        const float4* cp = reinterpret_cast<const float4*>(codebook + (gb + bi) * 8);
        float4* op = reinterpret_cast<float4*>(out + (size_t)grow * (CBN * 8) + cb * 8);
        op[0] = __ldg(cp);
        op[1] = __ldg(cp + 1);
        out[(size_t)B * (CBN * 8) + 1 + (size_t)grow * CBN + cb] = (float)bi;
        sm->bitsv[r] = __ldg(&g_p2[gb + bi]);
    }
    __syncthreads();

    // ---- per-CTA deterministic bits partial ----
    double* bd = sm->dscr;
    bd[tid] = (tid < RPC) ? (double)sm->bitsv[tid] : 0.0;
    __syncthreads();
    #pragma unroll
    for (int off = 128; off > 0; off >>= 1) {
        if (tid < off) bd[tid] += bd[tid + off];
        __syncthreads();
    }
    const int nCTA = gridDim.x * gridDim.y;
    if (tid == 0) {
        g_part[blockIdx.x * gridDim.y + blockIdx.y] = bd[0];
        __threadfence();
        unsigned int old = atomicAdd(&g_ctr, 1u);
        sm->flag = (old == (unsigned)(nCTA - 1)) ? 1 : 0;
    }
    __syncthreads();

    // ---- last CTA: deterministic final bits sum ----
    if (sm->flag) {
        double acc = 0.0;
        for (int i = tid; i < nCTA; i += TPB)
            acc += ((volatile double*)g_part)[i];
        __syncthreads();
        bd[tid] = acc;
        __syncthreads();
        #pragma unroll
        for (int off = 128; off > 0; off >>= 1) {
            if (tid < off) bd[tid] += bd[tid + off];
            __syncthreads();
        }
        if (tid == 0) {
            out[(size_t)B * (CBN * 8)] = (float)bd[0];
            g_ctr = 0;   // reset for next graph replay
        }
    }
}

extern "C" void kernel_launch(void* const* d_in, const int* in_sizes, int n_in,
                              void* d_out, int out_size)
{
    const float* x = nullptr; const float* codebook = nullptr; const float* logits = nullptr;
    int B = 0;
    for (int i = 0; i < n_in; i++) {
        if (in_sizes[i] == CBN * CSZ)          logits   = (const float*)d_in[i];
        else if (in_sizes[i] == CBN * CSZ * 8) codebook = (const float*)d_in[i];
        else { x = (const float*)d_in[i]; B = in_sizes[i] / (CBN * 8); }
    }
    float* out = (float*)d_out;

    size_t smem = sizeof(Smem);
    cudaFuncSetAttribute(ecvq_kernel,
                         cudaFuncAttributeMaxDynamicSharedMemorySize, (int)smem);

    prep_kernel<<<CBN, TPB>>>(codebook, logits);
    dim3 grid(CBN, B / RPC);
    ecvq_kernel<<<grid, TPB, smem>>>(x, codebook, out, B);
}

// round 12
// speedup vs baseline: 2.7233x; 1.2605x over previous
#include <cuda_runtime.h>
#include <cuda_bf16.h>
#include <stdint.h>
#include <math.h>

#define CBN 6
#define CSZ 1024
#define TPB 256
#define RPC 128          // rows per CTA (16 per warp)
#define EPS 0.25f        // rescue window: required ~0.10, 2.5x margin
#define QMAX 320         // per-warp queue entries; flush when qn >= QMAX-256

// per-lane-region b-frag layout: region (0..31) = g*4+t, stride 130 uint2
// (=1040B, odd 16B multiple -> conflict-free LDS.128), element nt at +nt.
__device__ __align__(16) uint2 g_bfrag[CBN * 32 * 130];
__device__ float  g_c2[CBN * CSZ];
__device__ float  g_L[CBN * CSZ];
__device__ float  g_p2[CBN * CSZ];
__device__ int    g_lc[CBN];
__device__ double g_part[CBN * 256];
__device__ unsigned int g_ctr = 0;

struct __align__(16) Smem {
    uint4  bfrag[32 * 65];            // 33280B
    float4 xfp[2 * RPC];              //  4096B exact fp32 x (rescue)
    unsigned short xaf[RPC * 8];      //  2048B bf16(-2x) a-frags
    float  x2sh[RPC];                 //   512B
    float  bitsv[RPC];                //   512B
    unsigned int qdat[8 * QMAX];      // 10240B per-warp rescue queues
    unsigned long long rbest[RPC];    //  1024B packed (val_bits<<32)|s per row
    double dscr[TPB];                 //  2048B
    int    flag;
};

__device__ __forceinline__ float sqrt_approx(float v) {
    float r; asm("sqrt.approx.f32 %0, %1;" : "=f"(r) : "f"(v)); return r;
}

__device__ __forceinline__ void hmma16816(float& d0, float& d1, float& d2, float& d3,
                                          uint32_t a0, uint32_t a1, uint32_t a2, uint32_t a3,
                                          uint32_t b0, uint32_t b1) {
    asm volatile(
        "mma.sync.aligned.m16n8k16.row.col.f32.bf16.bf16.f32 "
        "{%0,%1,%2,%3}, {%4,%5,%6,%7}, {%8,%9}, {%10,%11,%12,%13};"
        : "=f"(d0), "=f"(d1), "=f"(d2), "=f"(d3)
        : "r"(a0), "r"(a1), "r"(a2), "r"(a3), "r"(b0), "r"(b1),
          "f"(0.0f), "f"(0.0f), "f"(0.0f), "f"(0.0f));
}

// ---------------- prep: per-cb tables (proven numerics chain) ----------------
__global__ void __launch_bounds__(TPB) prep_kernel(
    const float* __restrict__ codebook,
    const float* __restrict__ logits)
{
    __shared__ float scr[TPB];
    const int tid = threadIdx.x;
    const int cb  = blockIdx.x;

    float4 lv = *reinterpret_cast<const float4*>(logits + (size_t)cb * CSZ + tid * 4);
    float lm = fmaxf(fmaxf(lv.x, lv.y), fmaxf(lv.z, lv.w));
    scr[tid] = lm; __syncthreads();
    #pragma unroll
    for (int off = 128; off > 0; off >>= 1) {
        if (tid < off) scr[tid] = fmaxf(scr[tid], scr[tid + off]);
        __syncthreads();
    }
    const float mx = scr[0]; __syncthreads();
    float lmn = fminf(fminf(lv.x, lv.y), fminf(lv.z, lv.w));
    scr[tid] = lmn; __syncthreads();
    #pragma unroll
    for (int off = 128; off > 0; off >>= 1) {
        if (tid < off) scr[tid] = fminf(scr[tid], scr[tid + off]);
        __syncthreads();
    }
    const bool lc = (scr[0] == mx);
    __syncthreads();
    float es = expf(lv.x - mx) + expf(lv.y - mx) + expf(lv.z - mx) + expf(lv.w - mx);
    scr[tid] = es; __syncthreads();
    #pragma unroll
    for (int off = 128; off > 0; off >>= 1) {
        if (tid < off) scr[tid] += scr[tid + off];
        __syncthreads();
    }
    const float lnS = logf(scr[0]);

    const float INV_LOG2 = 1.4426950408889634f;
    #pragma unroll
    for (int j = 0; j < 4; j++) {
        int s = tid * 4 + j;
        const float4* cp = reinterpret_cast<const float4*>(codebook + ((size_t)cb * CSZ + s) * 8);
        float4 c0 = cp[0], c1 = cp[1];
        float q0=c0.x*c0.x,q1=c0.y*c0.y,q2=c0.z*c0.z,q3=c0.w*c0.w;
        float q4=c1.x*c1.x,q5=c1.y*c1.y,q6=c1.z*c1.z,q7=c1.w*c1.w;
        float c2 = ((((((q0+q1)+q2)+q3)+q4)+q5)+q6)+q7;
        float v  = (j==0)?lv.x:(j==1)?lv.y:(j==2)?lv.z:lv.w;
        float p2 = ((v - mx) - lnS) * (-INV_LOG2);
        size_t gi = (size_t)cb * CSZ + s;
        g_c2[gi] = c2;
        g_L[gi]  = p2 / 0.005f;
        g_p2[gi] = p2;
        unsigned short e[8];
        e[0]=__bfloat16_as_ushort(__float2bfloat16_rn(c0.x));
        e[1]=__bfloat16_as_ushort(__float2bfloat16_rn(c0.y));
        e[2]=__bfloat16_as_ushort(__float2bfloat16_rn(c0.z));
        e[3]=__bfloat16_as_ushort(__float2bfloat16_rn(c0.w));
        e[4]=__bfloat16_as_ushort(__float2bfloat16_rn(c1.x));
        e[5]=__bfloat16_as_ushort(__float2bfloat16_rn(c1.y));
        e[6]=__bfloat16_as_ushort(__float2bfloat16_rn(c1.z));
        e[7]=__bfloat16_as_ushort(__float2bfloat16_rn(c1.w));
        unsigned short c2b = __bfloat16_as_ushort(__float2bfloat16_rn(c2));
        int nt = s >> 3, g = s & 7;
        uint2* base = &g_bfrag[(size_t)cb * 4160];
        #pragma unroll
        for (int t = 0; t < 4; t++) {
            uint32_t lo = (uint32_t)e[2*t] | ((uint32_t)e[2*t+1] << 16);
            uint32_t hi = (t == 0) ? (uint32_t)c2b : 0u;   // k8 = c2 (pairs a-frag 1.0)
            base[(g * 4 + t) * 130 + nt] = make_uint2(lo, hi);
        }
    }
    if (tid == 0) g_lc[cb] = lc ? 1 : 0;
}

// ---------------- main ----------------
__global__ void __launch_bounds__(TPB, 4)
ecvq_kernel(const float* __restrict__ x,
            const float* __restrict__ codebook,
            float* __restrict__ out, int B)
{
    extern __shared__ unsigned char smem_raw[];
    Smem* sm = reinterpret_cast<Smem*>(smem_raw);

    const int tid = threadIdx.x;
    const int cb  = blockIdx.x;
    const int rowBase = blockIdx.y * RPC;
    const float FINF = __int_as_float(0x7f800000);
    const size_t gb = (size_t)cb * CSZ;

    // ---- copy b-frag table from gmem (2080 uint4) ----
    {
        const uint4* src = reinterpret_cast<const uint4*>(&g_bfrag[(size_t)cb * 4160]);
        uint4* dst = sm->bfrag;
        #pragma unroll
        for (int i = 0; i < 8; i++) dst[tid + i * TPB] = src[tid + i * TPB];
        if (tid < 2080 - 8 * TPB) dst[tid + 8 * TPB] = src[tid + 8 * TPB];
    }
    const bool lc = (g_lc[cb] != 0);
    const float Lc = __ldg(&g_L[gb]);   // constant L when lc

    // ---- stage x (all 256 threads: half a row each) + init rbest ----
    {
        int r = tid >> 1;               // row 0..127
        int h = tid & 1;                // half
        int grow = rowBase + r;
        const float4* xpp = reinterpret_cast<const float4*>(
            x + (size_t)grow * (CBN * 8) + cb * 8) + h;
        float4 p = *xpp;
        sm->xfp[2 * r + h] = p;
        unsigned short* xa = &sm->xaf[r * 8 + h * 4];
        xa[0] = __bfloat16_as_ushort(__float2bfloat16_rn(-2.0f * p.x));
        xa[1] = __bfloat16_as_ushort(__float2bfloat16_rn(-2.0f * p.y));
        xa[2] = __bfloat16_as_ushort(__float2bfloat16_rn(-2.0f * p.z));
        xa[3] = __bfloat16_as_ushort(__float2bfloat16_rn(-2.0f * p.w));
        if (h == 0) sm->rbest[r] = ((unsigned long long)0x7f800000u << 32) | 0xFFFFFFFFull;
    }
    __syncthreads();
    // exact x2 (one thread per row, same fp32 chain as proven)
    if (tid < RPC) {
        float4 p0 = sm->xfp[2 * tid], p1 = sm->xfp[2 * tid + 1];
        float q0=p0.x*p0.x,q1=p0.y*p0.y,q2=p0.z*p0.z,q3=p0.w*p0.w;
        float q4=p1.x*p1.x,q5=p1.y*p1.y,q6=p1.z*p1.z,q7=p1.w*p1.w;
        sm->x2sh[tid] = ((((((q0+q1)+q2)+q3)+q4)+q5)+q6)+q7;
    }
    __syncthreads();

    // ---- warp tiling: each warp owns 16 rows ----
    const int warp = tid >> 5, lane = tid & 31;
    const int g = lane >> 2, t = lane & 3;
    const int r0 = warp * 16 + g, r1 = r0 + 8;

    const uint32_t a0 = *reinterpret_cast<const uint32_t*>(&sm->xaf[r0 * 8 + t * 2]);
    const uint32_t a1 = *reinterpret_cast<const uint32_t*>(&sm->xaf[r1 * 8 + t * 2]);
    const uint32_t ac = (t == 0) ? 0x00003F80u : 0u;   // bf16(1.0) at k8
    const unsigned lt = (1u << lane) - 1u;

    const char* bp = reinterpret_cast<const char*>(sm->bfrag) + lane * 1040;

    // exact rescore + publish (bit-exact proven chain; batched, warp-cooperative)
    auto flushq = [&](int n) {
        for (int b = 0; b < n; b += 32) {
            int i = b + lane;
            if (i < n) {
                unsigned e = sm->qdat[warp * QMAX + i];
                int s = (int)(e & 1023u), rl = (int)(e >> 10);
                int r = warp * 16 + rl;
                const float4* cp = reinterpret_cast<const float4*>(codebook + (gb + s) * 8);
                float4 ca = __ldg(cp), cv = __ldg(cp + 1);
                float4 pa = sm->xfp[2 * r], pb = sm->xfp[2 * r + 1];
                float xc = pa.x * ca.x;
                xc = fmaf(pa.y, ca.y, xc); xc = fmaf(pa.z, ca.z, xc); xc = fmaf(pa.w, ca.w, xc);
                xc = fmaf(pb.x, cv.x, xc); xc = fmaf(pb.y, cv.y, xc);
                xc = fmaf(pb.z, cv.z, xc); xc = fmaf(pb.w, cv.w, xc);
                float d2 = fmaf(-2.0f, xc, sm->x2sh[r]) + __ldg(&g_c2[gb + s]);
                float L  = lc ? Lc : __ldg(&g_L[gb + s]);
                float val = sqrt_approx(fmaxf(d2, 0.0f)) + L;
                unsigned long long pk =
                    ((unsigned long long)__float_as_uint(val) << 32) | (unsigned long long)(unsigned)s;
                atomicMin(&sm->rbest[r], pk);
            }
        }
    };

    // ============ PASS 1: branchless min of score = c2 - 2xc ============
    float m0 = FINF, m1 = FINF;
    #pragma unroll
    for (int it = 0; it < 64; it++) {
        uint4 q = *reinterpret_cast<const uint4*>(bp + it * 16);
        float d0, d1, d2, d3, e0, e1, e2, e3;
        hmma16816(d0, d1, d2, d3, a0, a1, ac, ac, q.x, q.y);
        hmma16816(e0, e1, e2, e3, a0, a1, ac, ac, q.z, q.w);
        m0 = fminf(m0, fminf(fminf(d0, d1), fminf(e0, e1)));
        m1 = fminf(m1, fminf(fminf(d2, d3), fminf(e2, e3)));
    }
    m0 = fminf(m0, __shfl_xor_sync(0xffffffffu, m0, 1));
    m0 = fminf(m0, __shfl_xor_sync(0xffffffffu, m0, 2));
    m1 = fminf(m1, __shfl_xor_sync(0xffffffffu, m1, 1));
    m1 = fminf(m1, __shfl_xor_sync(0xffffffffu, m1, 2));

    const float thr0 = lc ? m0 + EPS : FINF;
    const float thr1 = lc ? m1 + EPS : FINF;

    // ============ PASS 2: push window candidates to queue ============
    int qn = 0;   // warp-uniform queue count (ballot/popc maintained)

    #define PUSHQ(pred, sval, rlocal) do { \
        unsigned mk = __ballot_sync(0xffffffffu, (pred)); \
        if (pred) sm->qdat[warp * QMAX + qn + __popc(mk & lt)] = \
            (unsigned)((sval) | ((rlocal) << 10)); \
        qn += __popc(mk); \
    } while (0)

    #pragma unroll 8
    for (int it = 0; it < 64; it++) {
        uint4 q = *reinterpret_cast<const uint4*>(bp + it * 16);
        float d0, d1, d2, d3, e0, e1, e2, e3;
        hmma16816(d0, d1, d2, d3, a0, a1, ac, ac, q.x, q.y);
        hmma16816(e0, e1, e2, e3, a0, a1, ac, ac, q.z, q.w);
        bool anyT = (fminf(fminf(d0, d1), fminf(e0, e1)) < thr0)
                  | (fminf(fminf(d2, d3), fminf(e2, e3)) < thr1);
        if (__ballot_sync(0xffffffffu, anyT)) {
            if (qn >= QMAX - 256) { flushq(qn); __syncwarp(); qn = 0; }
            int sA = (2 * it) * 8 + 2 * t;
            int sB = sA + 8;
            PUSHQ(d0 < thr0, sA,     g);
            PUSHQ(d1 < thr0, sA + 1, g);
            PUSHQ(d2 < thr1, sA,     g + 8);
            PUSHQ(d3 < thr1, sA + 1, g + 8);
            PUSHQ(e0 < thr0, sB,     g);
            PUSHQ(e1 < thr0, sB + 1, g);
            PUSHQ(e2 < thr1, sB,     g + 8);
            PUSHQ(e3 < thr1, sB + 1, g + 8);
        }
    }
    __syncwarp();
    flushq(qn);
    __syncwarp();

    // ---- epilogue: lanes 0..15 write their row's winner ----
    if (lane < 16) {
        int r = warp * 16 + lane;
        unsigned long long w = sm->rbest[r];
        int bi = (int)(unsigned)(w & 0xFFFFFFFFull);
        int grow = rowBase + r;
        const float4* cp = reinterpret_cast<const float4*>(codebook + (gb + bi) * 8);
        float4* op = reinterpret_cast<float4*>(out + (size_t)grow * (CBN * 8) + cb * 8);
        op[0] = __ldg(cp);
        op[1] = __ldg(cp + 1);
        out[(size_t)B * (CBN * 8) + 1 + (size_t)grow * CBN + cb] = (float)bi;
        sm->bitsv[r] = __ldg(&g_p2[gb + bi]);
    }
    __syncthreads();

    // ---- per-CTA deterministic bits partial ----
    double* bd = sm->dscr;
    bd[tid] = (tid < RPC) ? (double)sm->bitsv[tid] : 0.0;
    __syncthreads();
    #pragma unroll
    for (int off = 128; off > 0; off >>= 1) {
        if (tid < off) bd[tid] += bd[tid + off];
        __syncthreads();
    }
    const int nCTA = gridDim.x * gridDim.y;
    if (tid == 0) {
        g_part[blockIdx.x * gridDim.y + blockIdx.y] = bd[0];
        __threadfence();
        unsigned int old = atomicAdd(&g_ctr, 1u);
        sm->flag = (old == (unsigned)(nCTA - 1)) ? 1 : 0;
    }
    __syncthreads();

    // ---- last CTA: deterministic final bits sum ----
    if (sm->flag) {
        double acc = 0.0;
        for (int i = tid; i < nCTA; i += TPB)
            acc += ((volatile double*)g_part)[i];
        __syncthreads();
        bd[tid] = acc;
        __syncthreads();
        #pragma unroll
        for (int off = 128; off > 0; off >>= 1) {
            if (tid < off) bd[tid] += bd[tid + off];
            __syncthreads();
        }
        if (tid == 0) {
            out[(size_t)B * (CBN * 8)] = (float)bd[0];
            g_ctr = 0;   // reset for next graph replay
        }
    }
}

extern "C" void kernel_launch(void* const* d_in, const int* in_sizes, int n_in,
                              void* d_out, int out_size)
{
    const float* x = nullptr; const float* codebook = nullptr; const float* logits = nullptr;
    int B = 0;
    for (int i = 0; i < n_in; i++) {
        if (in_sizes[i] == CBN * CSZ)          logits   = (const float*)d_in[i];
        else if (in_sizes[i] == CBN * CSZ * 8) codebook = (const float*)d_in[i];
        else { x = (const float*)d_in[i]; B = in_sizes[i] / (CBN * 8); }
    }
    float* out = (float*)d_out;

    size_t smem = sizeof(Smem);
    cudaFuncSetAttribute(ecvq_kernel,
                         cudaFuncAttributeMaxDynamicSharedMemorySize, (int)smem);

    prep_kernel<<<CBN, TPB>>>(codebook, logits);
    dim3 grid(CBN, B / RPC);
    ecvq_kernel<<<grid, TPB, smem>>>(x, codebook, out, B);
}